// round 7
// baseline (speedup 1.0000x reference)
#include <cuda_runtime.h>
#include <cstdint>

#define DIM   192
#define HEADS 6
#define HDIM  32
#define NTOK  64
#define NWIN  4096

// ---------------------------------------------------------------------------
// Scratch (static device globals — no allocation in kernel_launch)
// ---------------------------------------------------------------------------
// qkv laid out as (b, s, h, n, d): each (b,s,h) tile is a contiguous 64x32 block
__device__ float g_qkv[(size_t)NWIN * 3 * HEADS * NTOK * HDIM];   // ~604 MB
__device__ float g_att[(size_t)NWIN * NTOK * DIM];                // ~201 MB
__device__ float g_bias[HEADS * NTOK * NTOK];                     // 96 KB

// ---------------------------------------------------------------------------
// Packed f32x2 helpers (Blackwell FFMA2 path — 2 FMAs per instruction)
// ---------------------------------------------------------------------------
__device__ __forceinline__ unsigned long long pk2(float x) {
    unsigned long long r;
    unsigned int b = __float_as_uint(x);
    asm("mov.b64 %0, {%1, %1};" : "=l"(r) : "r"(b));
    return r;
}
__device__ __forceinline__ unsigned long long pk2f(float lo, float hi) {
    unsigned long long r;
    asm("mov.b64 %0, {%1, %2};" : "=l"(r) : "r"(__float_as_uint(lo)), "r"(__float_as_uint(hi)));
    return r;
}
__device__ __forceinline__ float2 upk2(unsigned long long v) {
    unsigned int lo, hi;
    asm("mov.b64 {%0, %1}, %2;" : "=r"(lo), "=r"(hi) : "l"(v));
    return make_float2(__uint_as_float(lo), __uint_as_float(hi));
}
__device__ __forceinline__ void ffma2(unsigned long long& d,
                                      unsigned long long a,
                                      unsigned long long b) {
    asm("fma.rn.f32x2 %0, %1, %2, %0;" : "+l"(d) : "l"(a), "l"(b));
}

// ---------------------------------------------------------------------------
// K0: materialize relative position bias: g_bias[h][i][j]
// ---------------------------------------------------------------------------
__global__ void bias_kernel(const float* __restrict__ rpb,
                            const int*   __restrict__ rel_idx) {
    int idx = blockIdx.x * blockDim.x + threadIdx.x;
    if (idx < HEADS * NTOK * NTOK) {
        int h = idx / (NTOK * NTOK);
        int r = idx % (NTOK * NTOK);
        g_bias[idx] = rpb[rel_idx[r] * HEADS + h];
    }
}

// ---------------------------------------------------------------------------
// K1: QKV GEMM.  C(262144 x 576) = X(262144 x 192) * W^T + b
// Block = 64 rows (one window) x 64 cols. 256 threads, 4x4 microtile, FFMA2.
// Epilogue scatters into g_qkv (b,s,h,n,d), scaling q by d^-0.5.
// ---------------------------------------------------------------------------
__global__ void __launch_bounds__(256) qkv_kernel(const float* __restrict__ x,
                                                  const float* __restrict__ w,
                                                  const float* __restrict__ bvec) {
    __shared__ float As[64][36];   // [row][k], padded for 16B-aligned float4 STS
    __shared__ float Bs[32][66];   // [k][col], padded (8B-aligned float2 LDS)

    const int tid = threadIdx.x;
    const int tx  = tid & 15, ty = tid >> 4;
    const int b       = blockIdx.y;
    const int rowBase = b * 64;
    const int colBase = blockIdx.x * 64;

    unsigned long long acc[4][2];
#pragma unroll
    for (int i = 0; i < 4; i++) { acc[i][0] = 0ULL; acc[i][1] = 0ULL; }

    for (int kt = 0; kt < DIM; kt += 32) {
#pragma unroll
        for (int it = 0; it < 2; it++) {
            int idx = tid + it * 256;
            int r = idx >> 3, c4 = (idx & 7) * 4;
            float4 va = *(const float4*)(x + (size_t)(rowBase + r) * DIM + kt + c4);
            *(float4*)(&As[r][c4]) = va;
            float4 vb = *(const float4*)(w + (size_t)(colBase + r) * DIM + kt + c4);
            Bs[c4 + 0][r] = vb.x; Bs[c4 + 1][r] = vb.y;
            Bs[c4 + 2][r] = vb.z; Bs[c4 + 3][r] = vb.w;
        }
        __syncthreads();
#pragma unroll 8
        for (int k = 0; k < 32; k++) {
            unsigned long long b0 = *(const unsigned long long*)(&Bs[k][tx * 4]);
            unsigned long long b1 = *(const unsigned long long*)(&Bs[k][tx * 4 + 2]);
#pragma unroll
            for (int i = 0; i < 4; i++) {
                unsigned long long a = pk2(As[ty * 4 + i][k]);
                ffma2(acc[i][0], a, b0);
                ffma2(acc[i][1], a, b1);
            }
        }
        __syncthreads();
    }

    // Epilogue: +bias, scale q, scatter to (b,s,h,n,d)
    const float scale = 0.17677669529663687f;   // 32^-0.5
    const int o0 = colBase + tx * 4;            // 4 contiguous output cols
    const int s  = o0 / DIM;                    // 0=q, 1=k, 2=v (tile never crosses)
    const int h  = (o0 % DIM) / HDIM;           // 4 cols stay within one head
    const int dd = o0 % HDIM;
    const float mul = (s == 0) ? scale : 1.0f;

#pragma unroll
    for (int i = 0; i < 4; i++) {
        int n = ty * 4 + i;
        float2 p0 = upk2(acc[i][0]);
        float2 p1 = upk2(acc[i][1]);
        float4 o4 = make_float4((p0.x + bvec[o0 + 0]) * mul,
                                (p0.y + bvec[o0 + 1]) * mul,
                                (p1.x + bvec[o0 + 2]) * mul,
                                (p1.y + bvec[o0 + 3]) * mul);
        *(float4*)(g_qkv + (((size_t)(b * 3 + s) * HEADS + h) * NTOK + n) * HDIM + dd) = o4;
    }
}

// ---------------------------------------------------------------------------
// K2: attention per (window, head). 24576 blocks x 256 threads.
//   logits = q_scaled . k^T + bias ; softmax rows ; out = attn . v
// ---------------------------------------------------------------------------
__global__ void __launch_bounds__(256) attn_kernel() {
    __shared__ float qs [64][36];   // [n][d]
    __shared__ float kts[32][66];   // [d][n]  (k transposed)
    __shared__ float vs [64][36];   // [n][d]
    __shared__ float as_[64][66];   // attn weights

    const int tid = threadIdx.x;
    const int bh  = blockIdx.x;
    const int b   = bh / HEADS, h = bh % HEADS;

    const float* qg = g_qkv + (((size_t)(b * 3 + 0) * HEADS + h) * NTOK) * HDIM;
    const float* kg = g_qkv + (((size_t)(b * 3 + 1) * HEADS + h) * NTOK) * HDIM;
    const float* vg = g_qkv + (((size_t)(b * 3 + 2) * HEADS + h) * NTOK) * HDIM;

#pragma unroll
    for (int it = 0; it < 2; it++) {
        int idx = tid + it * 256;
        int n = idx >> 3, c4 = (idx & 7) * 4;
        float4 q4 = *(const float4*)(qg + n * HDIM + c4);
        *(float4*)(&qs[n][c4]) = q4;
        float4 k4 = *(const float4*)(kg + n * HDIM + c4);
        kts[c4 + 0][n] = k4.x; kts[c4 + 1][n] = k4.y;
        kts[c4 + 2][n] = k4.z; kts[c4 + 3][n] = k4.w;
        float4 v4 = *(const float4*)(vg + n * HDIM + c4);
        *(float4*)(&vs[n][c4]) = v4;
    }
    __syncthreads();

    const int tx = tid & 15, ty = tid >> 4;   // rows ty*4..+3, cols tx*4..+3

    // init accumulators with bias (logit = q.k + bias)
    unsigned long long acc[4][2];
#pragma unroll
    for (int i = 0; i < 4; i++) {
        int row = ty * 4 + i;
        float4 bb = *(const float4*)(g_bias + h * (NTOK * NTOK) + row * NTOK + tx * 4);
        acc[i][0] = pk2f(bb.x, bb.y);
        acc[i][1] = pk2f(bb.z, bb.w);
    }
#pragma unroll 8
    for (int k = 0; k < HDIM; k++) {
        unsigned long long b0 = *(const unsigned long long*)(&kts[k][tx * 4]);
        unsigned long long b1 = *(const unsigned long long*)(&kts[k][tx * 4 + 2]);
#pragma unroll
        for (int i = 0; i < 4; i++) {
            unsigned long long a = pk2(qs[ty * 4 + i][k]);
            ffma2(acc[i][0], a, b0);
            ffma2(acc[i][1], a, b1);
        }
    }

    // softmax: each row owned by 16 lanes sharing ty; lane = (ty&1)*16 + tx,
    // so xor-butterfly offsets 1,2,4,8 stay inside the 16-lane group.
#pragma unroll
    for (int i = 0; i < 4; i++) {
        float2 p0 = upk2(acc[i][0]), p1 = upk2(acc[i][1]);
        float m = fmaxf(fmaxf(p0.x, p0.y), fmaxf(p1.x, p1.y));
#pragma unroll
        for (int off = 8; off >= 1; off >>= 1)
            m = fmaxf(m, __shfl_xor_sync(0xffffffffu, m, off));
        float e0 = __expf(p0.x - m), e1 = __expf(p0.y - m);
        float e2 = __expf(p1.x - m), e3 = __expf(p1.y - m);
        float ssum = e0 + e1 + e2 + e3;
#pragma unroll
        for (int off = 8; off >= 1; off >>= 1)
            ssum += __shfl_xor_sync(0xffffffffu, ssum, off);
        float inv = 1.0f / ssum;
        int row = ty * 4 + i;
        as_[row][tx * 4 + 0] = e0 * inv;
        as_[row][tx * 4 + 1] = e1 * inv;
        as_[row][tx * 4 + 2] = e2 * inv;
        as_[row][tx * 4 + 3] = e3 * inv;
    }
    __syncthreads();

    // out[i][dd] = sum_j attn[i][j] * v[j][dd]; thread -> (row i, 8 cols)
    const int i   = tid >> 2;
    const int dd0 = (tid & 3) * 8;
    unsigned long long o[4] = {0ULL, 0ULL, 0ULL, 0ULL};
#pragma unroll 8
    for (int j = 0; j < NTOK; j++) {
        unsigned long long a  = pk2(as_[i][j]);
        unsigned long long v0 = *(const unsigned long long*)(&vs[j][dd0]);
        unsigned long long v1 = *(const unsigned long long*)(&vs[j][dd0 + 2]);
        unsigned long long v2 = *(const unsigned long long*)(&vs[j][dd0 + 4]);
        unsigned long long v3 = *(const unsigned long long*)(&vs[j][dd0 + 6]);
        ffma2(o[0], a, v0); ffma2(o[1], a, v1);
        ffma2(o[2], a, v2); ffma2(o[3], a, v3);
    }
    float* dst = g_att + ((size_t)b * NTOK + i) * DIM + h * HDIM + dd0;
    float2 r0 = upk2(o[0]), r1 = upk2(o[1]), r2 = upk2(o[2]), r3 = upk2(o[3]);
    *(float4*)(dst)     = make_float4(r0.x, r0.y, r1.x, r1.y);
    *(float4*)(dst + 4) = make_float4(r2.x, r2.y, r3.x, r3.y);
}

// ---------------------------------------------------------------------------
// K3: proj GEMM. out(262144 x 192) = g_att * proj_w^T + proj_b
// ---------------------------------------------------------------------------
__global__ void __launch_bounds__(256) proj_kernel(const float* __restrict__ w,
                                                   const float* __restrict__ bvec,
                                                   float* __restrict__ out) {
    __shared__ float As[64][36];
    __shared__ float Bs[32][66];

    const int tid = threadIdx.x;
    const int tx  = tid & 15, ty = tid >> 4;
    const size_t rowBase = (size_t)blockIdx.y * 64;
    const int colBase    = blockIdx.x * 64;

    unsigned long long acc[4][2];
#pragma unroll
    for (int i = 0; i < 4; i++) { acc[i][0] = 0ULL; acc[i][1] = 0ULL; }

    for (int kt = 0; kt < DIM; kt += 32) {
#pragma unroll
        for (int it = 0; it < 2; it++) {
            int idx = tid + it * 256;
            int r = idx >> 3, c4 = (idx & 7) * 4;
            float4 va = *(const float4*)(g_att + (rowBase + r) * DIM + kt + c4);
            *(float4*)(&As[r][c4]) = va;
            float4 vb = *(const float4*)(w + (size_t)(colBase + r) * DIM + kt + c4);
            Bs[c4 + 0][r] = vb.x; Bs[c4 + 1][r] = vb.y;
            Bs[c4 + 2][r] = vb.z; Bs[c4 + 3][r] = vb.w;
        }
        __syncthreads();
#pragma unroll 8
        for (int k = 0; k < 32; k++) {
            unsigned long long b0 = *(const unsigned long long*)(&Bs[k][tx * 4]);
            unsigned long long b1 = *(const unsigned long long*)(&Bs[k][tx * 4 + 2]);
#pragma unroll
            for (int i = 0; i < 4; i++) {
                unsigned long long a = pk2(As[ty * 4 + i][k]);
                ffma2(acc[i][0], a, b0);
                ffma2(acc[i][1], a, b1);
            }
        }
        __syncthreads();
    }

    const int c0 = colBase + tx * 4;
#pragma unroll
    for (int i = 0; i < 4; i++) {
        size_t row = rowBase + ty * 4 + i;
        float2 p0 = upk2(acc[i][0]);
        float2 p1 = upk2(acc[i][1]);
        float4 o4 = make_float4(p0.x + bvec[c0 + 0],
                                p0.y + bvec[c0 + 1],
                                p1.x + bvec[c0 + 2],
                                p1.y + bvec[c0 + 3]);
        *(float4*)(out + row * DIM + c0) = o4;
    }
}

// ---------------------------------------------------------------------------
// Launch
// ---------------------------------------------------------------------------
extern "C" void kernel_launch(void* const* d_in, const int* in_sizes, int n_in,
                              void* d_out, int out_size) {
    (void)in_sizes; (void)n_in; (void)out_size;
    const float* x      = (const float*)d_in[0];
    const float* qkv_w  = (const float*)d_in[1];
    const float* qkv_b  = (const float*)d_in[2];
    const float* proj_w = (const float*)d_in[3];
    const float* proj_b = (const float*)d_in[4];
    const float* rpb    = (const float*)d_in[5];
    const int*   relid  = (const int*)d_in[6];
    float* out = (float*)d_out;

    bias_kernel<<<(HEADS * NTOK * NTOK + 255) / 256, 256>>>(rpb, relid);
    qkv_kernel<<<dim3(3 * DIM / 64, NWIN), 256>>>(x, qkv_w, qkv_b);
    attn_kernel<<<NWIN * HEADS, 256>>>();
    proj_kernel<<<dim3(DIM / 64, NWIN), 256>>>(proj_w, proj_b, out);
}

// round 8
// speedup vs baseline: 1.0002x; 1.0002x over previous
#include <cuda_runtime.h>
#include <cstdint>

#define DIM   192
#define HEADS 6
#define HDIM  32
#define NTOK  64
#define NWIN  4096

// ---------------------------------------------------------------------------
// Scratch (static device globals — no allocation in kernel_launch)
// ---------------------------------------------------------------------------
// qkv laid out as (b, s, h, n, d): each (b,s,h) tile is a contiguous 64x32 block
__device__ float g_qkv[(size_t)NWIN * 3 * HEADS * NTOK * HDIM];   // ~604 MB
__device__ float g_att[(size_t)NWIN * NTOK * DIM];                // ~201 MB
__device__ float g_bias[HEADS * NTOK * NTOK];                     // 96 KB

// ---------------------------------------------------------------------------
// Packed f32x2 helpers (Blackwell FFMA2 path — 2 FMAs per instruction)
// ---------------------------------------------------------------------------
__device__ __forceinline__ unsigned long long pk2(float x) {
    unsigned long long r;
    unsigned int b = __float_as_uint(x);
    asm("mov.b64 %0, {%1, %1};" : "=l"(r) : "r"(b));
    return r;
}
__device__ __forceinline__ unsigned long long pk2f(float lo, float hi) {
    unsigned long long r;
    asm("mov.b64 %0, {%1, %2};" : "=l"(r) : "r"(__float_as_uint(lo)), "r"(__float_as_uint(hi)));
    return r;
}
__device__ __forceinline__ float2 upk2(unsigned long long v) {
    unsigned int lo, hi;
    asm("mov.b64 {%0, %1}, %2;" : "=r"(lo), "=r"(hi) : "l"(v));
    return make_float2(__uint_as_float(lo), __uint_as_float(hi));
}
__device__ __forceinline__ void ffma2(unsigned long long& d,
                                      unsigned long long a,
                                      unsigned long long b) {
    asm("fma.rn.f32x2 %0, %1, %2, %0;" : "+l"(d) : "l"(a), "l"(b));
}

// ---------------------------------------------------------------------------
// K0: materialize relative position bias: g_bias[h][i][j]
// ---------------------------------------------------------------------------
__global__ void bias_kernel(const float* __restrict__ rpb,
                            const int*   __restrict__ rel_idx) {
    int idx = blockIdx.x * blockDim.x + threadIdx.x;
    if (idx < HEADS * NTOK * NTOK) {
        int h = idx / (NTOK * NTOK);
        int r = idx % (NTOK * NTOK);
        g_bias[idx] = rpb[rel_idx[r] * HEADS + h];
    }
}

// ---------------------------------------------------------------------------
// K1: QKV GEMM.  C(262144 x 576) = X(262144 x 192) * W^T + b
// Block = 64 rows (one window) x 64 cols. 256 threads, 4x4 microtile, FFMA2.
// Epilogue scatters into g_qkv (b,s,h,n,d), scaling q by d^-0.5.
// ---------------------------------------------------------------------------
__global__ void __launch_bounds__(256) qkv_kernel(const float* __restrict__ x,
                                                  const float* __restrict__ w,
                                                  const float* __restrict__ bvec) {
    __shared__ float As[64][36];   // [row][k], padded for 16B-aligned float4 STS
    __shared__ float Bs[32][66];   // [k][col], padded (8B-aligned float2 LDS)

    const int tid = threadIdx.x;
    const int tx  = tid & 15, ty = tid >> 4;
    const int b       = blockIdx.y;
    const int rowBase = b * 64;
    const int colBase = blockIdx.x * 64;

    unsigned long long acc[4][2];
#pragma unroll
    for (int i = 0; i < 4; i++) { acc[i][0] = 0ULL; acc[i][1] = 0ULL; }

    for (int kt = 0; kt < DIM; kt += 32) {
#pragma unroll
        for (int it = 0; it < 2; it++) {
            int idx = tid + it * 256;
            int r = idx >> 3, c4 = (idx & 7) * 4;
            float4 va = *(const float4*)(x + (size_t)(rowBase + r) * DIM + kt + c4);
            *(float4*)(&As[r][c4]) = va;
            float4 vb = *(const float4*)(w + (size_t)(colBase + r) * DIM + kt + c4);
            Bs[c4 + 0][r] = vb.x; Bs[c4 + 1][r] = vb.y;
            Bs[c4 + 2][r] = vb.z; Bs[c4 + 3][r] = vb.w;
        }
        __syncthreads();
#pragma unroll 8
        for (int k = 0; k < 32; k++) {
            unsigned long long b0 = *(const unsigned long long*)(&Bs[k][tx * 4]);
            unsigned long long b1 = *(const unsigned long long*)(&Bs[k][tx * 4 + 2]);
#pragma unroll
            for (int i = 0; i < 4; i++) {
                unsigned long long a = pk2(As[ty * 4 + i][k]);
                ffma2(acc[i][0], a, b0);
                ffma2(acc[i][1], a, b1);
            }
        }
        __syncthreads();
    }

    // Epilogue: +bias, scale q, scatter to (b,s,h,n,d)
    const float scale = 0.17677669529663687f;   // 32^-0.5
    const int o0 = colBase + tx * 4;            // 4 contiguous output cols
    const int s  = o0 / DIM;                    // 0=q, 1=k, 2=v (tile never crosses)
    const int h  = (o0 % DIM) / HDIM;           // 4 cols stay within one head
    const int dd = o0 % HDIM;
    const float mul = (s == 0) ? scale : 1.0f;

#pragma unroll
    for (int i = 0; i < 4; i++) {
        int n = ty * 4 + i;
        float2 p0 = upk2(acc[i][0]);
        float2 p1 = upk2(acc[i][1]);
        float4 o4 = make_float4((p0.x + bvec[o0 + 0]) * mul,
                                (p0.y + bvec[o0 + 1]) * mul,
                                (p1.x + bvec[o0 + 2]) * mul,
                                (p1.y + bvec[o0 + 3]) * mul);
        *(float4*)(g_qkv + (((size_t)(b * 3 + s) * HEADS + h) * NTOK + n) * HDIM + dd) = o4;
    }
}

// ---------------------------------------------------------------------------
// K2: attention per (window, head). 24576 blocks x 256 threads.
//   logits = q_scaled . k^T + bias ; softmax rows ; out = attn . v
// ---------------------------------------------------------------------------
__global__ void __launch_bounds__(256) attn_kernel() {
    __shared__ float qs [64][36];   // [n][d]
    __shared__ float kts[32][66];   // [d][n]  (k transposed)
    __shared__ float vs [64][36];   // [n][d]
    __shared__ float as_[64][66];   // attn weights

    const int tid = threadIdx.x;
    const int bh  = blockIdx.x;
    const int b   = bh / HEADS, h = bh % HEADS;

    const float* qg = g_qkv + (((size_t)(b * 3 + 0) * HEADS + h) * NTOK) * HDIM;
    const float* kg = g_qkv + (((size_t)(b * 3 + 1) * HEADS + h) * NTOK) * HDIM;
    const float* vg = g_qkv + (((size_t)(b * 3 + 2) * HEADS + h) * NTOK) * HDIM;

#pragma unroll
    for (int it = 0; it < 2; it++) {
        int idx = tid + it * 256;
        int n = idx >> 3, c4 = (idx & 7) * 4;
        float4 q4 = *(const float4*)(qg + n * HDIM + c4);
        *(float4*)(&qs[n][c4]) = q4;
        float4 k4 = *(const float4*)(kg + n * HDIM + c4);
        kts[c4 + 0][n] = k4.x; kts[c4 + 1][n] = k4.y;
        kts[c4 + 2][n] = k4.z; kts[c4 + 3][n] = k4.w;
        float4 v4 = *(const float4*)(vg + n * HDIM + c4);
        *(float4*)(&vs[n][c4]) = v4;
    }
    __syncthreads();

    const int tx = tid & 15, ty = tid >> 4;   // rows ty*4..+3, cols tx*4..+3

    // init accumulators with bias (logit = q.k + bias)
    unsigned long long acc[4][2];
#pragma unroll
    for (int i = 0; i < 4; i++) {
        int row = ty * 4 + i;
        float4 bb = *(const float4*)(g_bias + h * (NTOK * NTOK) + row * NTOK + tx * 4);
        acc[i][0] = pk2f(bb.x, bb.y);
        acc[i][1] = pk2f(bb.z, bb.w);
    }
#pragma unroll 8
    for (int k = 0; k < HDIM; k++) {
        unsigned long long b0 = *(const unsigned long long*)(&kts[k][tx * 4]);
        unsigned long long b1 = *(const unsigned long long*)(&kts[k][tx * 4 + 2]);
#pragma unroll
        for (int i = 0; i < 4; i++) {
            unsigned long long a = pk2(qs[ty * 4 + i][k]);
            ffma2(acc[i][0], a, b0);
            ffma2(acc[i][1], a, b1);
        }
    }

    // softmax: each row owned by 16 lanes sharing ty; lane = (ty&1)*16 + tx,
    // so xor-butterfly offsets 1,2,4,8 stay inside the 16-lane group.
#pragma unroll
    for (int i = 0; i < 4; i++) {
        float2 p0 = upk2(acc[i][0]), p1 = upk2(acc[i][1]);
        float m = fmaxf(fmaxf(p0.x, p0.y), fmaxf(p1.x, p1.y));
#pragma unroll
        for (int off = 8; off >= 1; off >>= 1)
            m = fmaxf(m, __shfl_xor_sync(0xffffffffu, m, off));
        float e0 = __expf(p0.x - m), e1 = __expf(p0.y - m);
        float e2 = __expf(p1.x - m), e3 = __expf(p1.y - m);
        float ssum = e0 + e1 + e2 + e3;
#pragma unroll
        for (int off = 8; off >= 1; off >>= 1)
            ssum += __shfl_xor_sync(0xffffffffu, ssum, off);
        float inv = 1.0f / ssum;
        int row = ty * 4 + i;
        as_[row][tx * 4 + 0] = e0 * inv;
        as_[row][tx * 4 + 1] = e1 * inv;
        as_[row][tx * 4 + 2] = e2 * inv;
        as_[row][tx * 4 + 3] = e3 * inv;
    }
    __syncthreads();

    // out[i][dd] = sum_j attn[i][j] * v[j][dd]; thread -> (row i, 8 cols)
    const int i   = tid >> 2;
    const int dd0 = (tid & 3) * 8;
    unsigned long long o[4] = {0ULL, 0ULL, 0ULL, 0ULL};
#pragma unroll 8
    for (int j = 0; j < NTOK; j++) {
        unsigned long long a  = pk2(as_[i][j]);
        unsigned long long v0 = *(const unsigned long long*)(&vs[j][dd0]);
        unsigned long long v1 = *(const unsigned long long*)(&vs[j][dd0 + 2]);
        unsigned long long v2 = *(const unsigned long long*)(&vs[j][dd0 + 4]);
        unsigned long long v3 = *(const unsigned long long*)(&vs[j][dd0 + 6]);
        ffma2(o[0], a, v0); ffma2(o[1], a, v1);
        ffma2(o[2], a, v2); ffma2(o[3], a, v3);
    }
    float* dst = g_att + ((size_t)b * NTOK + i) * DIM + h * HDIM + dd0;
    float2 r0 = upk2(o[0]), r1 = upk2(o[1]), r2 = upk2(o[2]), r3 = upk2(o[3]);
    *(float4*)(dst)     = make_float4(r0.x, r0.y, r1.x, r1.y);
    *(float4*)(dst + 4) = make_float4(r2.x, r2.y, r3.x, r3.y);
}

// ---------------------------------------------------------------------------
// K3: proj GEMM. out(262144 x 192) = g_att * proj_w^T + proj_b
// ---------------------------------------------------------------------------
__global__ void __launch_bounds__(256) proj_kernel(const float* __restrict__ w,
                                                   const float* __restrict__ bvec,
                                                   float* __restrict__ out) {
    __shared__ float As[64][36];
    __shared__ float Bs[32][66];

    const int tid = threadIdx.x;
    const int tx  = tid & 15, ty = tid >> 4;
    const size_t rowBase = (size_t)blockIdx.y * 64;
    const int colBase    = blockIdx.x * 64;

    unsigned long long acc[4][2];
#pragma unroll
    for (int i = 0; i < 4; i++) { acc[i][0] = 0ULL; acc[i][1] = 0ULL; }

    for (int kt = 0; kt < DIM; kt += 32) {
#pragma unroll
        for (int it = 0; it < 2; it++) {
            int idx = tid + it * 256;
            int r = idx >> 3, c4 = (idx & 7) * 4;
            float4 va = *(const float4*)(g_att + (rowBase + r) * DIM + kt + c4);
            *(float4*)(&As[r][c4]) = va;
            float4 vb = *(const float4*)(w + (size_t)(colBase + r) * DIM + kt + c4);
            Bs[c4 + 0][r] = vb.x; Bs[c4 + 1][r] = vb.y;
            Bs[c4 + 2][r] = vb.z; Bs[c4 + 3][r] = vb.w;
        }
        __syncthreads();
#pragma unroll 8
        for (int k = 0; k < 32; k++) {
            unsigned long long b0 = *(const unsigned long long*)(&Bs[k][tx * 4]);
            unsigned long long b1 = *(const unsigned long long*)(&Bs[k][tx * 4 + 2]);
#pragma unroll
            for (int i = 0; i < 4; i++) {
                unsigned long long a = pk2(As[ty * 4 + i][k]);
                ffma2(acc[i][0], a, b0);
                ffma2(acc[i][1], a, b1);
            }
        }
        __syncthreads();
    }

    const int c0 = colBase + tx * 4;
#pragma unroll
    for (int i = 0; i < 4; i++) {
        size_t row = rowBase + ty * 4 + i;
        float2 p0 = upk2(acc[i][0]);
        float2 p1 = upk2(acc[i][1]);
        float4 o4 = make_float4(p0.x + bvec[c0 + 0],
                                p0.y + bvec[c0 + 1],
                                p1.x + bvec[c0 + 2],
                                p1.y + bvec[c0 + 3]);
        *(float4*)(out + row * DIM + c0) = o4;
    }
}

// ---------------------------------------------------------------------------
// Launch
// ---------------------------------------------------------------------------
extern "C" void kernel_launch(void* const* d_in, const int* in_sizes, int n_in,
                              void* d_out, int out_size) {
    (void)in_sizes; (void)n_in; (void)out_size;
    const float* x      = (const float*)d_in[0];
    const float* qkv_w  = (const float*)d_in[1];
    const float* qkv_b  = (const float*)d_in[2];
    const float* proj_w = (const float*)d_in[3];
    const float* proj_b = (const float*)d_in[4];
    const float* rpb    = (const float*)d_in[5];
    const int*   relid  = (const int*)d_in[6];
    float* out = (float*)d_out;

    bias_kernel<<<(HEADS * NTOK * NTOK + 255) / 256, 256>>>(rpb, relid);
    qkv_kernel<<<dim3(3 * DIM / 64, NWIN), 256>>>(x, qkv_w, qkv_b);
    attn_kernel<<<NWIN * HEADS, 256>>>();
    proj_kernel<<<dim3(DIM / 64, NWIN), 256>>>(proj_w, proj_b, out);
}

// round 10
// speedup vs baseline: 1.7168x; 1.7165x over previous
#include <cuda_runtime.h>
#include <cuda_bf16.h>
#include <cstdint>

#define DIM   192
#define HEADS 6
#define HDIM  32
#define NTOK  64
#define NWIN  4096

// ---------------------------------------------------------------------------
// Scratch (static device globals — no allocation in kernel_launch)
// ---------------------------------------------------------------------------
__device__ float g_qkv[(size_t)NWIN * 3 * HEADS * NTOK * HDIM];   // (b,s,h,n,d)
__device__ float g_att[(size_t)NWIN * NTOK * DIM];
__device__ float g_bias[HEADS * NTOK * NTOK];

// ---------------------------------------------------------------------------
// Helpers
// ---------------------------------------------------------------------------
__device__ __forceinline__ uint32_t smem_to_u32(const void* smem_ptr) {
    uint32_t addr;
    asm("{ .reg .u64 tmp; cvta.to.shared.u64 tmp, %1; cvt.u32.u64 %0, tmp; }"
        : "=r"(addr) : "l"(smem_ptr));
    return addr;
}

// ldmatrix x4 (baseline PTX, sm_75+ — no arch suffix needed)
__device__ __forceinline__ void ldm_x4(uint32_t* r, uint32_t addr) {
    asm volatile("ldmatrix.sync.aligned.m8n8.x4.shared.b16 {%0,%1,%2,%3}, [%4];"
                 : "=r"(r[0]), "=r"(r[1]), "=r"(r[2]), "=r"(r[3]) : "r"(addr));
}

// mma.sync m16n8k16 bf16 -> fp32 (baseline PTX, sm_80+)
__device__ __forceinline__ void mma16816(float* c, const uint32_t* a,
                                         uint32_t b0, uint32_t b1) {
    asm volatile(
        "mma.sync.aligned.m16n8k16.row.col.f32.bf16.bf16.f32 "
        "{%0,%1,%2,%3}, {%4,%5,%6,%7}, {%8,%9}, {%0,%1,%2,%3};"
        : "+f"(c[0]), "+f"(c[1]), "+f"(c[2]), "+f"(c[3])
        : "r"(a[0]), "r"(a[1]), "r"(a[2]), "r"(a[3]), "r"(b0), "r"(b1));
}

// ---------------------------------------------------------------------------
// Packed f32x2 helpers (attention kernel)
// ---------------------------------------------------------------------------
__device__ __forceinline__ unsigned long long pk2(float x) {
    unsigned long long r;
    unsigned int b = __float_as_uint(x);
    asm("mov.b64 %0, {%1, %1};" : "=l"(r) : "r"(b));
    return r;
}
__device__ __forceinline__ unsigned long long pk2f(float lo, float hi) {
    unsigned long long r;
    asm("mov.b64 %0, {%1, %2};" : "=l"(r) : "r"(__float_as_uint(lo)), "r"(__float_as_uint(hi)));
    return r;
}
__device__ __forceinline__ float2 upk2(unsigned long long v) {
    unsigned int lo, hi;
    asm("mov.b64 {%0, %1}, %2;" : "=r"(lo), "=r"(hi) : "l"(v));
    return make_float2(__uint_as_float(lo), __uint_as_float(hi));
}
__device__ __forceinline__ void ffma2(unsigned long long& d,
                                      unsigned long long a,
                                      unsigned long long b) {
    asm("fma.rn.f32x2 %0, %1, %2, %0;" : "+l"(d) : "l"(a), "l"(b));
}

// ---------------------------------------------------------------------------
// bf16 hi/lo split of 4 floats, packed for 8-byte smem stores
// ---------------------------------------------------------------------------
__device__ __forceinline__ void split4(float4 v, uint2& hi, uint2& lo) {
    __nv_bfloat16 hx = __float2bfloat16(v.x), hy = __float2bfloat16(v.y);
    __nv_bfloat16 hz = __float2bfloat16(v.z), hw = __float2bfloat16(v.w);
    float rx = v.x - __bfloat162float(hx), ry = v.y - __bfloat162float(hy);
    float rz = v.z - __bfloat162float(hz), rw = v.w - __bfloat162float(hw);
    __nv_bfloat16 lx = __float2bfloat16(rx), ly = __float2bfloat16(ry);
    __nv_bfloat16 lz = __float2bfloat16(rz), lw = __float2bfloat16(rw);
    hi.x = (uint32_t)__bfloat16_as_ushort(hx) | ((uint32_t)__bfloat16_as_ushort(hy) << 16);
    hi.y = (uint32_t)__bfloat16_as_ushort(hz) | ((uint32_t)__bfloat16_as_ushort(hw) << 16);
    lo.x = (uint32_t)__bfloat16_as_ushort(lx) | ((uint32_t)__bfloat16_as_ushort(ly) << 16);
    lo.y = (uint32_t)__bfloat16_as_ushort(lz) | ((uint32_t)__bfloat16_as_ushort(lw) << 16);
}

// ---------------------------------------------------------------------------
// Shared memory layout (byte offsets). Row pitch = 400B (192 bf16 + 8 pad):
// pitch/16 = 25 chunks -> ldmatrix rows land on distinct 4-bank groups
// (4r mod 32), conflict-free.
// ---------------------------------------------------------------------------
#define PITCH      400u
#define A_LO_OFF   51200u          // A hi: [0,51200), A lo: [51200,102400)
#define B_BASE     102400u         // 2 stages x (hi 25600 + lo 25600)
#define B_LO_OFF   25600u
#define B_STRIDE   51200u
#define SMEM_BYTES 204800u

// ---------------------------------------------------------------------------
// K0: materialize relative position bias
// ---------------------------------------------------------------------------
__global__ void bias_kernel(const float* __restrict__ rpb,
                            const int*   __restrict__ rel_idx) {
    int idx = blockIdx.x * blockDim.x + threadIdx.x;
    if (idx < HEADS * NTOK * NTOK) {
        int h = idx / (NTOK * NTOK);
        int r = idx % (NTOK * NTOK);
        g_bias[idx] = rpb[rel_idx[r] * HEADS + h];
    }
}

// ---------------------------------------------------------------------------
// Tensor-core GEMM via mma.sync:  C[128 rows, CT*64 cols] = A(.,192) @ W^T + b
// bf16 hi/lo 3-pass split accumulated in fp32 registers.
// QKV=true: A=x, scatter epilogue into g_qkv (scale q). QKV=false: A=g_att, C=Out.
// ---------------------------------------------------------------------------
template<int CT, bool QKV>
__global__ void __launch_bounds__(256, 1)
gemm_kernel(const float* __restrict__ Ain, const float* __restrict__ W,
            const float* __restrict__ bvec, float* __restrict__ Out)
{
    extern __shared__ __align__(16) char smem[];
    const uint32_t sb = smem_to_u32(smem);
    const int tid = threadIdx.x;
    const int wid = tid >> 5, lid = tid & 31;
    const int rowBase = blockIdx.x * 128;
    const int warpRow = (wid & 3) * 32;
    const int warpCol = (wid >> 2) * 32;

    const float* Asrc = QKV ? Ain : (const float*)g_att;

    // ---- load + split A tile (128 x 192) into hi/lo bf16 ----
#pragma unroll
    for (int i = 0; i < 24; i++) {
        int idx = tid + i * 256;                 // 6144 float4s
        int r = idx / 48, k4 = (idx % 48) * 4;
        float4 v = *(const float4*)(Asrc + (size_t)(rowBase + r) * DIM + k4);
        uint2 hi, lo; split4(v, hi, lo);
        *(uint2*)(smem + r * PITCH + k4 * 2) = hi;
        *(uint2*)(smem + A_LO_OFF + r * PITCH + k4 * 2) = lo;
    }
    // ---- load + split B tile 0 (64 x 192) into stage 0 ----
#pragma unroll
    for (int i = 0; i < 12; i++) {
        int idx = tid + i * 256;                 // 3072 float4s
        int r = idx / 48, k4 = (idx % 48) * 4;
        float4 v = *(const float4*)(W + (size_t)r * DIM + k4);
        uint2 hi, lo; split4(v, hi, lo);
        *(uint2*)(smem + B_BASE + r * PITCH + k4 * 2) = hi;
        *(uint2*)(smem + B_BASE + B_LO_OFF + r * PITCH + k4 * 2) = lo;
    }
    __syncthreads();

    // per-lane ldmatrix address components
    const int lrow = (lid & 7) + ((lid >> 3) & 1) * 8;
    const int lkb  = (lid >> 4) * 16;            // k-offset in bytes
    const uint32_t aoff0 = (uint32_t)((warpRow + lrow) * PITCH) + lkb;
    const uint32_t aoff1 = aoff0 + 16 * PITCH;
    const uint32_t boff0 = (uint32_t)((warpCol + lrow) * PITCH) + lkb;
    const uint32_t boff1 = boff0 + 16 * PITCH;

    for (int ct = 0; ct < CT; ct++) {
        float acc[2][4][4];
#pragma unroll
        for (int mt = 0; mt < 2; mt++)
#pragma unroll
            for (int nt = 0; nt < 4; nt++)
#pragma unroll
                for (int e = 0; e < 4; e++) acc[mt][nt][e] = 0.0f;

        // register-staged prefetch of next B tile (hidden under MMA loop)
        float4 stage[12];
        const bool have_next = (ct + 1 < CT);
        if (have_next) {
#pragma unroll
            for (int i = 0; i < 12; i++) {
                int idx = tid + i * 256;
                int r = idx / 48, k4 = (idx % 48) * 4;
                stage[i] = *(const float4*)(W + (size_t)((ct + 1) * 64 + r) * DIM + k4);
            }
        }

        const uint32_t bstage = B_BASE + (uint32_t)(ct & 1) * B_STRIDE;
#pragma unroll
        for (int pass = 0; pass < 3; pass++) {
            const uint32_t ab = sb + (pass == 2 ? A_LO_OFF : 0u);
            const uint32_t bb = sb + bstage + (pass == 1 ? B_LO_OFF : 0u);
#pragma unroll
            for (int ks = 0; ks < 12; ks++) {
                uint32_t A0[4], A1[4], B0[4], B1[4];
                ldm_x4(A0, ab + aoff0 + ks * 32);
                ldm_x4(A1, ab + aoff1 + ks * 32);
                ldm_x4(B0, bb + boff0 + ks * 32);
                ldm_x4(B1, bb + boff1 + ks * 32);
                mma16816(acc[0][0], A0, B0[0], B0[2]);
                mma16816(acc[0][1], A0, B0[1], B0[3]);
                mma16816(acc[0][2], A0, B1[0], B1[2]);
                mma16816(acc[0][3], A0, B1[1], B1[3]);
                mma16816(acc[1][0], A1, B0[0], B0[2]);
                mma16816(acc[1][1], A1, B0[1], B0[3]);
                mma16816(acc[1][2], A1, B1[0], B1[2]);
                mma16816(acc[1][3], A1, B1[1], B1[3]);
            }
        }

        // convert staged B into the other buffer (readers of it synced last iter)
        if (have_next) {
            const uint32_t bs2 = B_BASE + (uint32_t)((ct + 1) & 1) * B_STRIDE;
#pragma unroll
            for (int i = 0; i < 12; i++) {
                int idx = tid + i * 256;
                int r = idx / 48, k4 = (idx % 48) * 4;
                uint2 hi, lo; split4(stage[i], hi, lo);
                *(uint2*)(smem + bs2 + r * PITCH + k4 * 2) = hi;
                *(uint2*)(smem + bs2 + B_LO_OFF + r * PITCH + k4 * 2) = lo;
            }
        }

        // ---- epilogue ----
        const int g  = lid >> 2;
        const int c2 = (lid & 3) * 2;
#pragma unroll
        for (int mt = 0; mt < 2; mt++) {
            const int r0 = rowBase + warpRow + mt * 16 + g;
#pragma unroll
            for (int nt = 0; nt < 4; nt++) {
                const int colg = ct * 64 + warpCol + nt * 8 + c2;
                const float bv0 = bvec[colg], bv1 = bvec[colg + 1];
                if (QKV) {
                    const int s = colg / DIM, rem = colg % DIM;
                    const int h = rem >> 5, dd = rem & 31;
                    const float mul = (s == 0) ? 0.17677669529663687f : 1.0f;
#pragma unroll
                    for (int hh = 0; hh < 2; hh++) {
                        const int row = r0 + hh * 8;
                        const int bw = row >> 6, n = row & 63;
                        float2 o = make_float2((acc[mt][nt][hh * 2 + 0] + bv0) * mul,
                                               (acc[mt][nt][hh * 2 + 1] + bv1) * mul);
                        *(float2*)(g_qkv + ((((size_t)bw * 3 + s) * HEADS + h) * NTOK + n) * HDIM + dd) = o;
                    }
                } else {
#pragma unroll
                    for (int hh = 0; hh < 2; hh++) {
                        const int row = r0 + hh * 8;
                        float2 o = make_float2(acc[mt][nt][hh * 2 + 0] + bv0,
                                               acc[mt][nt][hh * 2 + 1] + bv1);
                        *(float2*)(Out + (size_t)row * DIM + colg) = o;
                    }
                }
            }
        }
        __syncthreads();
    }
}

// ---------------------------------------------------------------------------
// K2: attention per (window, head) — FFMA2 version (unchanged, passing)
// ---------------------------------------------------------------------------
__global__ void __launch_bounds__(256) attn_kernel() {
    __shared__ float qs [64][36];
    __shared__ float kts[32][66];
    __shared__ float vs [64][36];
    __shared__ float as_[64][66];

    const int tid = threadIdx.x;
    const int bh  = blockIdx.x;
    const int b   = bh / HEADS, h = bh % HEADS;

    const float* qg = g_qkv + (((size_t)(b * 3 + 0) * HEADS + h) * NTOK) * HDIM;
    const float* kg = g_qkv + (((size_t)(b * 3 + 1) * HEADS + h) * NTOK) * HDIM;
    const float* vg = g_qkv + (((size_t)(b * 3 + 2) * HEADS + h) * NTOK) * HDIM;

#pragma unroll
    for (int it = 0; it < 2; it++) {
        int idx = tid + it * 256;
        int n = idx >> 3, c4 = (idx & 7) * 4;
        float4 q4 = *(const float4*)(qg + n * HDIM + c4);
        *(float4*)(&qs[n][c4]) = q4;
        float4 k4 = *(const float4*)(kg + n * HDIM + c4);
        kts[c4 + 0][n] = k4.x; kts[c4 + 1][n] = k4.y;
        kts[c4 + 2][n] = k4.z; kts[c4 + 3][n] = k4.w;
        float4 v4 = *(const float4*)(vg + n * HDIM + c4);
        *(float4*)(&vs[n][c4]) = v4;
    }
    __syncthreads();

    const int tx = tid & 15, ty = tid >> 4;

    unsigned long long acc[4][2];
#pragma unroll
    for (int i = 0; i < 4; i++) {
        int row = ty * 4 + i;
        float4 bb = *(const float4*)(g_bias + h * (NTOK * NTOK) + row * NTOK + tx * 4);
        acc[i][0] = pk2f(bb.x, bb.y);
        acc[i][1] = pk2f(bb.z, bb.w);
    }
#pragma unroll 8
    for (int k = 0; k < HDIM; k++) {
        unsigned long long b0 = *(const unsigned long long*)(&kts[k][tx * 4]);
        unsigned long long b1 = *(const unsigned long long*)(&kts[k][tx * 4 + 2]);
#pragma unroll
        for (int i = 0; i < 4; i++) {
            unsigned long long a = pk2(qs[ty * 4 + i][k]);
            ffma2(acc[i][0], a, b0);
            ffma2(acc[i][1], a, b1);
        }
    }

#pragma unroll
    for (int i = 0; i < 4; i++) {
        float2 p0 = upk2(acc[i][0]), p1 = upk2(acc[i][1]);
        float m = fmaxf(fmaxf(p0.x, p0.y), fmaxf(p1.x, p1.y));
#pragma unroll
        for (int off = 8; off >= 1; off >>= 1)
            m = fmaxf(m, __shfl_xor_sync(0xffffffffu, m, off));
        float e0 = __expf(p0.x - m), e1 = __expf(p0.y - m);
        float e2 = __expf(p1.x - m), e3 = __expf(p1.y - m);
        float ssum = e0 + e1 + e2 + e3;
#pragma unroll
        for (int off = 8; off >= 1; off >>= 1)
            ssum += __shfl_xor_sync(0xffffffffu, ssum, off);
        float inv = 1.0f / ssum;
        int row = ty * 4 + i;
        as_[row][tx * 4 + 0] = e0 * inv;
        as_[row][tx * 4 + 1] = e1 * inv;
        as_[row][tx * 4 + 2] = e2 * inv;
        as_[row][tx * 4 + 3] = e3 * inv;
    }
    __syncthreads();

    const int i   = tid >> 2;
    const int dd0 = (tid & 3) * 8;
    unsigned long long o[4] = {0ULL, 0ULL, 0ULL, 0ULL};
#pragma unroll 8
    for (int j = 0; j < NTOK; j++) {
        unsigned long long a  = pk2(as_[i][j]);
        unsigned long long v0 = *(const unsigned long long*)(&vs[j][dd0]);
        unsigned long long v1 = *(const unsigned long long*)(&vs[j][dd0 + 2]);
        unsigned long long v2 = *(const unsigned long long*)(&vs[j][dd0 + 4]);
        unsigned long long v3 = *(const unsigned long long*)(&vs[j][dd0 + 6]);
        ffma2(o[0], a, v0); ffma2(o[1], a, v1);
        ffma2(o[2], a, v2); ffma2(o[3], a, v3);
    }
    float* dst = g_att + ((size_t)b * NTOK + i) * DIM + h * HDIM + dd0;
    float2 r0 = upk2(o[0]), r1 = upk2(o[1]), r2 = upk2(o[2]), r3 = upk2(o[3]);
    *(float4*)(dst)     = make_float4(r0.x, r0.y, r1.x, r1.y);
    *(float4*)(dst + 4) = make_float4(r2.x, r2.y, r3.x, r3.y);
}

// ---------------------------------------------------------------------------
// Launch
// ---------------------------------------------------------------------------
extern "C" void kernel_launch(void* const* d_in, const int* in_sizes, int n_in,
                              void* d_out, int out_size) {
    (void)in_sizes; (void)n_in; (void)out_size;
    const float* x      = (const float*)d_in[0];
    const float* qkv_w  = (const float*)d_in[1];
    const float* qkv_b  = (const float*)d_in[2];
    const float* proj_w = (const float*)d_in[3];
    const float* proj_b = (const float*)d_in[4];
    const float* rpb    = (const float*)d_in[5];
    const int*   relid  = (const int*)d_in[6];
    float* out = (float*)d_out;

    cudaFuncSetAttribute(gemm_kernel<9, true>,
                         cudaFuncAttributeMaxDynamicSharedMemorySize, SMEM_BYTES);
    cudaFuncSetAttribute(gemm_kernel<3, false>,
                         cudaFuncAttributeMaxDynamicSharedMemorySize, SMEM_BYTES);

    bias_kernel<<<(HEADS * NTOK * NTOK + 255) / 256, 256>>>(rpb, relid);
    gemm_kernel<9, true><<<NWIN * NTOK / 128, 256, SMEM_BYTES>>>(x, qkv_w, qkv_b, nullptr);
    attn_kernel<<<NWIN * HEADS, 256>>>();
    gemm_kernel<3, false><<<NWIN * NTOK / 128, 256, SMEM_BYTES>>>(nullptr, proj_w, proj_b, out);
}

// round 11
// speedup vs baseline: 1.7268x; 1.0059x over previous
#include <cuda_runtime.h>
#include <cuda_bf16.h>
#include <cstdint>

#define DIM   192
#define HEADS 6
#define HDIM  32
#define NTOK  64
#define NWIN  4096

// ---------------------------------------------------------------------------
// Scratch (static device globals — no allocation in kernel_launch)
// ---------------------------------------------------------------------------
__device__ float g_qkv[(size_t)NWIN * 3 * HEADS * NTOK * HDIM];   // (b,s,h,n,d)
__device__ float g_att[(size_t)NWIN * NTOK * DIM];
__device__ float g_bias[HEADS * NTOK * NTOK];

// ---------------------------------------------------------------------------
// Helpers
// ---------------------------------------------------------------------------
__device__ __forceinline__ uint32_t smem_to_u32(const void* smem_ptr) {
    uint32_t addr;
    asm("{ .reg .u64 tmp; cvta.to.shared.u64 tmp, %1; cvt.u32.u64 %0, tmp; }"
        : "=r"(addr) : "l"(smem_ptr));
    return addr;
}

// ldmatrix x4 (baseline PTX, sm_75+ — no arch suffix needed)
__device__ __forceinline__ void ldm_x4(uint32_t* r, uint32_t addr) {
    asm volatile("ldmatrix.sync.aligned.m8n8.x4.shared.b16 {%0,%1,%2,%3}, [%4];"
                 : "=r"(r[0]), "=r"(r[1]), "=r"(r[2]), "=r"(r[3]) : "r"(addr));
}

// mma.sync m16n8k16 bf16 -> fp32 (baseline PTX, sm_80+)
__device__ __forceinline__ void mma16816(float* c, const uint32_t* a,
                                         uint32_t b0, uint32_t b1) {
    asm volatile(
        "mma.sync.aligned.m16n8k16.row.col.f32.bf16.bf16.f32 "
        "{%0,%1,%2,%3}, {%4,%5,%6,%7}, {%8,%9}, {%0,%1,%2,%3};"
        : "+f"(c[0]), "+f"(c[1]), "+f"(c[2]), "+f"(c[3])
        : "r"(a[0]), "r"(a[1]), "r"(a[2]), "r"(a[3]), "r"(b0), "r"(b1));
}

// ---------------------------------------------------------------------------
// Packed f32x2 helpers (attention kernel)
// ---------------------------------------------------------------------------
__device__ __forceinline__ unsigned long long pk2(float x) {
    unsigned long long r;
    unsigned int b = __float_as_uint(x);
    asm("mov.b64 %0, {%1, %1};" : "=l"(r) : "r"(b));
    return r;
}
__device__ __forceinline__ unsigned long long pk2f(float lo, float hi) {
    unsigned long long r;
    asm("mov.b64 %0, {%1, %2};" : "=l"(r) : "r"(__float_as_uint(lo)), "r"(__float_as_uint(hi)));
    return r;
}
__device__ __forceinline__ float2 upk2(unsigned long long v) {
    unsigned int lo, hi;
    asm("mov.b64 {%0, %1}, %2;" : "=r"(lo), "=r"(hi) : "l"(v));
    return make_float2(__uint_as_float(lo), __uint_as_float(hi));
}
__device__ __forceinline__ void ffma2(unsigned long long& d,
                                      unsigned long long a,
                                      unsigned long long b) {
    asm("fma.rn.f32x2 %0, %1, %2, %0;" : "+l"(d) : "l"(a), "l"(b));
}

// ---------------------------------------------------------------------------
// bf16 hi/lo split of 4 floats, packed for 8-byte smem stores
// ---------------------------------------------------------------------------
__device__ __forceinline__ void split4(float4 v, uint2& hi, uint2& lo) {
    __nv_bfloat16 hx = __float2bfloat16(v.x), hy = __float2bfloat16(v.y);
    __nv_bfloat16 hz = __float2bfloat16(v.z), hw = __float2bfloat16(v.w);
    float rx = v.x - __bfloat162float(hx), ry = v.y - __bfloat162float(hy);
    float rz = v.z - __bfloat162float(hz), rw = v.w - __bfloat162float(hw);
    __nv_bfloat16 lx = __float2bfloat16(rx), ly = __float2bfloat16(ry);
    __nv_bfloat16 lz = __float2bfloat16(rz), lw = __float2bfloat16(rw);
    hi.x = (uint32_t)__bfloat16_as_ushort(hx) | ((uint32_t)__bfloat16_as_ushort(hy) << 16);
    hi.y = (uint32_t)__bfloat16_as_ushort(hz) | ((uint32_t)__bfloat16_as_ushort(hw) << 16);
    lo.x = (uint32_t)__bfloat16_as_ushort(lx) | ((uint32_t)__bfloat16_as_ushort(ly) << 16);
    lo.y = (uint32_t)__bfloat16_as_ushort(lz) | ((uint32_t)__bfloat16_as_ushort(lw) << 16);
}

// ---------------------------------------------------------------------------
// Shared memory layout (byte offsets). Row pitch = 400B (192 bf16 + 8 pad):
// pitch/16 = 25 chunks -> ldmatrix rows land on distinct 4-bank groups
// (4r mod 32), conflict-free.
// ---------------------------------------------------------------------------
#define PITCH      400u
#define A_LO_OFF   51200u          // A hi: [0,51200), A lo: [51200,102400)
#define B_BASE     102400u         // 2 stages x (hi 25600 + lo 25600)
#define B_LO_OFF   25600u
#define B_STRIDE   51200u
#define SMEM_BYTES 204800u

// ---------------------------------------------------------------------------
// K0: materialize relative position bias
// ---------------------------------------------------------------------------
__global__ void bias_kernel(const float* __restrict__ rpb,
                            const int*   __restrict__ rel_idx) {
    int idx = blockIdx.x * blockDim.x + threadIdx.x;
    if (idx < HEADS * NTOK * NTOK) {
        int h = idx / (NTOK * NTOK);
        int r = idx % (NTOK * NTOK);
        g_bias[idx] = rpb[rel_idx[r] * HEADS + h];
    }
}

// ---------------------------------------------------------------------------
// Tensor-core GEMM via mma.sync:  C[128 rows, CT*64 cols] = A(.,192) @ W^T + b
// bf16 hi/lo 3-pass split accumulated in fp32 registers.
// QKV=true: A=x, scatter epilogue into g_qkv (scale q). QKV=false: A=g_att, C=Out.
// ---------------------------------------------------------------------------
template<int CT, bool QKV>
__global__ void __launch_bounds__(256, 1)
gemm_kernel(const float* __restrict__ Ain, const float* __restrict__ W,
            const float* __restrict__ bvec, float* __restrict__ Out)
{
    extern __shared__ __align__(16) char smem[];
    const uint32_t sb = smem_to_u32(smem);
    const int tid = threadIdx.x;
    const int wid = tid >> 5, lid = tid & 31;
    const int rowBase = blockIdx.x * 128;
    const int warpRow = (wid & 3) * 32;
    const int warpCol = (wid >> 2) * 32;

    const float* Asrc = QKV ? Ain : (const float*)g_att;

    // ---- load + split A tile (128 x 192) into hi/lo bf16 ----
#pragma unroll
    for (int i = 0; i < 24; i++) {
        int idx = tid + i * 256;                 // 6144 float4s
        int r = idx / 48, k4 = (idx % 48) * 4;
        float4 v = *(const float4*)(Asrc + (size_t)(rowBase + r) * DIM + k4);
        uint2 hi, lo; split4(v, hi, lo);
        *(uint2*)(smem + r * PITCH + k4 * 2) = hi;
        *(uint2*)(smem + A_LO_OFF + r * PITCH + k4 * 2) = lo;
    }
    // ---- load + split B tile 0 (64 x 192) into stage 0 ----
#pragma unroll
    for (int i = 0; i < 12; i++) {
        int idx = tid + i * 256;                 // 3072 float4s
        int r = idx / 48, k4 = (idx % 48) * 4;
        float4 v = *(const float4*)(W + (size_t)r * DIM + k4);
        uint2 hi, lo; split4(v, hi, lo);
        *(uint2*)(smem + B_BASE + r * PITCH + k4 * 2) = hi;
        *(uint2*)(smem + B_BASE + B_LO_OFF + r * PITCH + k4 * 2) = lo;
    }
    __syncthreads();

    // per-lane ldmatrix address components
    const int lrow = (lid & 7) + ((lid >> 3) & 1) * 8;
    const int lkb  = (lid >> 4) * 16;            // k-offset in bytes
    const uint32_t aoff0 = (uint32_t)((warpRow + lrow) * PITCH) + lkb;
    const uint32_t aoff1 = aoff0 + 16 * PITCH;
    const uint32_t boff0 = (uint32_t)((warpCol + lrow) * PITCH) + lkb;
    const uint32_t boff1 = boff0 + 16 * PITCH;

    for (int ct = 0; ct < CT; ct++) {
        float acc[2][4][4];
#pragma unroll
        for (int mt = 0; mt < 2; mt++)
#pragma unroll
            for (int nt = 0; nt < 4; nt++)
#pragma unroll
                for (int e = 0; e < 4; e++) acc[mt][nt][e] = 0.0f;

        // register-staged prefetch of next B tile (hidden under MMA loop)
        float4 stage[12];
        const bool have_next = (ct + 1 < CT);
        if (have_next) {
#pragma unroll
            for (int i = 0; i < 12; i++) {
                int idx = tid + i * 256;
                int r = idx / 48, k4 = (idx % 48) * 4;
                stage[i] = *(const float4*)(W + (size_t)((ct + 1) * 64 + r) * DIM + k4);
            }
        }

        const uint32_t bstage = B_BASE + (uint32_t)(ct & 1) * B_STRIDE;
#pragma unroll
        for (int pass = 0; pass < 3; pass++) {
            const uint32_t ab = sb + (pass == 2 ? A_LO_OFF : 0u);
            const uint32_t bb = sb + bstage + (pass == 1 ? B_LO_OFF : 0u);
#pragma unroll
            for (int ks = 0; ks < 12; ks++) {
                uint32_t A0[4], A1[4], B0[4], B1[4];
                ldm_x4(A0, ab + aoff0 + ks * 32);
                ldm_x4(A1, ab + aoff1 + ks * 32);
                ldm_x4(B0, bb + boff0 + ks * 32);
                ldm_x4(B1, bb + boff1 + ks * 32);
                mma16816(acc[0][0], A0, B0[0], B0[2]);
                mma16816(acc[0][1], A0, B0[1], B0[3]);
                mma16816(acc[0][2], A0, B1[0], B1[2]);
                mma16816(acc[0][3], A0, B1[1], B1[3]);
                mma16816(acc[1][0], A1, B0[0], B0[2]);
                mma16816(acc[1][1], A1, B0[1], B0[3]);
                mma16816(acc[1][2], A1, B1[0], B1[2]);
                mma16816(acc[1][3], A1, B1[1], B1[3]);
            }
        }

        // convert staged B into the other buffer (readers of it synced last iter)
        if (have_next) {
            const uint32_t bs2 = B_BASE + (uint32_t)((ct + 1) & 1) * B_STRIDE;
#pragma unroll
            for (int i = 0; i < 12; i++) {
                int idx = tid + i * 256;
                int r = idx / 48, k4 = (idx % 48) * 4;
                uint2 hi, lo; split4(stage[i], hi, lo);
                *(uint2*)(smem + bs2 + r * PITCH + k4 * 2) = hi;
                *(uint2*)(smem + bs2 + B_LO_OFF + r * PITCH + k4 * 2) = lo;
            }
        }

        // ---- epilogue ----
        const int g  = lid >> 2;
        const int c2 = (lid & 3) * 2;
#pragma unroll
        for (int mt = 0; mt < 2; mt++) {
            const int r0 = rowBase + warpRow + mt * 16 + g;
#pragma unroll
            for (int nt = 0; nt < 4; nt++) {
                const int colg = ct * 64 + warpCol + nt * 8 + c2;
                const float bv0 = bvec[colg], bv1 = bvec[colg + 1];
                if (QKV) {
                    const int s = colg / DIM, rem = colg % DIM;
                    const int h = rem >> 5, dd = rem & 31;
                    const float mul = (s == 0) ? 0.17677669529663687f : 1.0f;
#pragma unroll
                    for (int hh = 0; hh < 2; hh++) {
                        const int row = r0 + hh * 8;
                        const int bw = row >> 6, n = row & 63;
                        float2 o = make_float2((acc[mt][nt][hh * 2 + 0] + bv0) * mul,
                                               (acc[mt][nt][hh * 2 + 1] + bv1) * mul);
                        *(float2*)(g_qkv + ((((size_t)bw * 3 + s) * HEADS + h) * NTOK + n) * HDIM + dd) = o;
                    }
                } else {
#pragma unroll
                    for (int hh = 0; hh < 2; hh++) {
                        const int row = r0 + hh * 8;
                        float2 o = make_float2(acc[mt][nt][hh * 2 + 0] + bv0,
                                               acc[mt][nt][hh * 2 + 1] + bv1);
                        *(float2*)(Out + (size_t)row * DIM + colg) = o;
                    }
                }
            }
        }
        __syncthreads();
    }
}

// ---------------------------------------------------------------------------
// K2: attention per (window, head) — FFMA2 version (unchanged, passing)
// ---------------------------------------------------------------------------
__global__ void __launch_bounds__(256) attn_kernel() {
    __shared__ float qs [64][36];
    __shared__ float kts[32][66];
    __shared__ float vs [64][36];
    __shared__ float as_[64][66];

    const int tid = threadIdx.x;
    const int bh  = blockIdx.x;
    const int b   = bh / HEADS, h = bh % HEADS;

    const float* qg = g_qkv + (((size_t)(b * 3 + 0) * HEADS + h) * NTOK) * HDIM;
    const float* kg = g_qkv + (((size_t)(b * 3 + 1) * HEADS + h) * NTOK) * HDIM;
    const float* vg = g_qkv + (((size_t)(b * 3 + 2) * HEADS + h) * NTOK) * HDIM;

#pragma unroll
    for (int it = 0; it < 2; it++) {
        int idx = tid + it * 256;
        int n = idx >> 3, c4 = (idx & 7) * 4;
        float4 q4 = *(const float4*)(qg + n * HDIM + c4);
        *(float4*)(&qs[n][c4]) = q4;
        float4 k4 = *(const float4*)(kg + n * HDIM + c4);
        kts[c4 + 0][n] = k4.x; kts[c4 + 1][n] = k4.y;
        kts[c4 + 2][n] = k4.z; kts[c4 + 3][n] = k4.w;
        float4 v4 = *(const float4*)(vg + n * HDIM + c4);
        *(float4*)(&vs[n][c4]) = v4;
    }
    __syncthreads();

    const int tx = tid & 15, ty = tid >> 4;

    unsigned long long acc[4][2];
#pragma unroll
    for (int i = 0; i < 4; i++) {
        int row = ty * 4 + i;
        float4 bb = *(const float4*)(g_bias + h * (NTOK * NTOK) + row * NTOK + tx * 4);
        acc[i][0] = pk2f(bb.x, bb.y);
        acc[i][1] = pk2f(bb.z, bb.w);
    }
#pragma unroll 8
    for (int k = 0; k < HDIM; k++) {
        unsigned long long b0 = *(const unsigned long long*)(&kts[k][tx * 4]);
        unsigned long long b1 = *(const unsigned long long*)(&kts[k][tx * 4 + 2]);
#pragma unroll
        for (int i = 0; i < 4; i++) {
            unsigned long long a = pk2(qs[ty * 4 + i][k]);
            ffma2(acc[i][0], a, b0);
            ffma2(acc[i][1], a, b1);
        }
    }

#pragma unroll
    for (int i = 0; i < 4; i++) {
        float2 p0 = upk2(acc[i][0]), p1 = upk2(acc[i][1]);
        float m = fmaxf(fmaxf(p0.x, p0.y), fmaxf(p1.x, p1.y));
#pragma unroll
        for (int off = 8; off >= 1; off >>= 1)
            m = fmaxf(m, __shfl_xor_sync(0xffffffffu, m, off));
        float e0 = __expf(p0.x - m), e1 = __expf(p0.y - m);
        float e2 = __expf(p1.x - m), e3 = __expf(p1.y - m);
        float ssum = e0 + e1 + e2 + e3;
#pragma unroll
        for (int off = 8; off >= 1; off >>= 1)
            ssum += __shfl_xor_sync(0xffffffffu, ssum, off);
        float inv = 1.0f / ssum;
        int row = ty * 4 + i;
        as_[row][tx * 4 + 0] = e0 * inv;
        as_[row][tx * 4 + 1] = e1 * inv;
        as_[row][tx * 4 + 2] = e2 * inv;
        as_[row][tx * 4 + 3] = e3 * inv;
    }
    __syncthreads();

    const int i   = tid >> 2;
    const int dd0 = (tid & 3) * 8;
    unsigned long long o[4] = {0ULL, 0ULL, 0ULL, 0ULL};
#pragma unroll 8
    for (int j = 0; j < NTOK; j++) {
        unsigned long long a  = pk2(as_[i][j]);
        unsigned long long v0 = *(const unsigned long long*)(&vs[j][dd0]);
        unsigned long long v1 = *(const unsigned long long*)(&vs[j][dd0 + 2]);
        unsigned long long v2 = *(const unsigned long long*)(&vs[j][dd0 + 4]);
        unsigned long long v3 = *(const unsigned long long*)(&vs[j][dd0 + 6]);
        ffma2(o[0], a, v0); ffma2(o[1], a, v1);
        ffma2(o[2], a, v2); ffma2(o[3], a, v3);
    }
    float* dst = g_att + ((size_t)b * NTOK + i) * DIM + h * HDIM + dd0;
    float2 r0 = upk2(o[0]), r1 = upk2(o[1]), r2 = upk2(o[2]), r3 = upk2(o[3]);
    *(float4*)(dst)     = make_float4(r0.x, r0.y, r1.x, r1.y);
    *(float4*)(dst + 4) = make_float4(r2.x, r2.y, r3.x, r3.y);
}

// ---------------------------------------------------------------------------
// Launch
// ---------------------------------------------------------------------------
extern "C" void kernel_launch(void* const* d_in, const int* in_sizes, int n_in,
                              void* d_out, int out_size) {
    (void)in_sizes; (void)n_in; (void)out_size;
    const float* x      = (const float*)d_in[0];
    const float* qkv_w  = (const float*)d_in[1];
    const float* qkv_b  = (const float*)d_in[2];
    const float* proj_w = (const float*)d_in[3];
    const float* proj_b = (const float*)d_in[4];
    const float* rpb    = (const float*)d_in[5];
    const int*   relid  = (const int*)d_in[6];
    float* out = (float*)d_out;

    cudaFuncSetAttribute(gemm_kernel<9, true>,
                         cudaFuncAttributeMaxDynamicSharedMemorySize, SMEM_BYTES);
    cudaFuncSetAttribute(gemm_kernel<3, false>,
                         cudaFuncAttributeMaxDynamicSharedMemorySize, SMEM_BYTES);

    bias_kernel<<<(HEADS * NTOK * NTOK + 255) / 256, 256>>>(rpb, relid);
    gemm_kernel<9, true><<<NWIN * NTOK / 128, 256, SMEM_BYTES>>>(x, qkv_w, qkv_b, nullptr);
    attn_kernel<<<NWIN * HEADS, 256>>>();
    gemm_kernel<3, false><<<NWIN * NTOK / 128, 256, SMEM_BYTES>>>(nullptr, proj_w, proj_b, out);
}